// round 8
// baseline (speedup 1.0000x reference)
#include <cuda_runtime.h>
#include <stdint.h>

#define NN 50000
#define DD 128
#define RR 16
#define EE 1600000
#define NSEG (NN * RR)   // 800000 (dst-major, rel-minor segments)

// ---------------- device scratch (no allocs allowed) ----------------
__device__ __align__(16) float g_msg[(size_t)RR * NN * DD];  // tf32-rounded scaled means
__device__ __align__(16) float g_h1[(size_t)NN * DD];        // layer-1 output (raw fp32)
__device__ __align__(16) float g_xr[(size_t)NN * DD];        // tf32-rounded x (L1) / h1 (L2)
__device__ __align__(16) float g_wr[2 * 17 * DD * DD];       // tf32-rounded [W_r..., root] x2 layers
__device__ int   g_cnt[NSEG];
__device__ __align__(16) float g_inv[NSEG];
__device__ int   g_off[NSEG + 1];
__device__ int   g_cursor[NSEG];
__device__ unsigned long long g_rec[EE];   // packed (dst | src<<20 | rel<<40)
__device__ unsigned int g_csr[EE];         // seg-sorted: src
__device__ int   g_is64;

// ---------------- helpers ----------------
__device__ __forceinline__ float tf32r(float x) {
    uint32_t u;
    asm("cvt.rna.tf32.f32 %0, %1;" : "=r"(u) : "f"(x));
    return __uint_as_float(u);
}

__device__ __forceinline__ void mma8(float* c, const uint32_t* a, const uint32_t* b) {
    asm volatile(
        "mma.sync.aligned.m16n8k8.row.col.f32.tf32.tf32.f32 "
        "{%0,%1,%2,%3}, {%4,%5,%6,%7}, {%8,%9}, {%0,%1,%2,%3};"
        : "+f"(c[0]), "+f"(c[1]), "+f"(c[2]), "+f"(c[3])
        : "r"(a[0]), "r"(a[1]), "r"(a[2]), "r"(a[3]), "r"(b[0]), "r"(b[1]));
}

__device__ __forceinline__ void cp16(uint32_t saddr, const void* gaddr, int srcsize) {
    asm volatile("cp.async.cg.shared.global [%0], [%1], 16, %2;"
                 :: "r"(saddr), "l"(gaddr), "r"(srcsize));
}

// ---------------- dtype detector ----------------
__global__ void detect_kernel(const unsigned int* __restrict__ et_words) {
    __shared__ int any_nonzero;
    if (threadIdx.x == 0) any_nonzero = 0;
    __syncthreads();
    for (int i = threadIdx.x; i < 2048; i += blockDim.x) {
        if (et_words[2 * i + 1] != 0u) any_nonzero = 1;
    }
    __syncthreads();
    if (threadIdx.x == 0) g_is64 = any_nonzero ? 0 : 1;
}

// ---------------- setup ----------------
__global__ void zero_cnt_kernel() {
    int i = blockIdx.x * blockDim.x + threadIdx.x;
    for (; i < NSEG; i += gridDim.x * blockDim.x) g_cnt[i] = 0;
}

__global__ void count_kernel(const void* __restrict__ ei_raw,
                             const void* __restrict__ et_raw) {
    const int is64 = g_is64;
    int e = blockIdx.x * blockDim.x + threadIdx.x;
    for (; e < EE; e += gridDim.x * blockDim.x) {
        int s, d, r;
        if (is64) {
            const long long* ei = (const long long*)ei_raw;
            const long long* et = (const long long*)et_raw;
            s = (int)ei[e];
            d = (int)ei[(size_t)EE + e];
            r = (int)et[e];
        } else {
            const int* ei = (const int*)ei_raw;
            const int* et = (const int*)et_raw;
            s = ei[e];
            d = ei[EE + e];
            r = et[e];
        }
        if ((unsigned)s >= NN || (unsigned)d >= NN || (unsigned)r >= RR) {
            g_rec[e] = ~0ull;
            continue;
        }
        g_rec[e] = (unsigned long long)d
                 | ((unsigned long long)s << 20)
                 | ((unsigned long long)r << 40);
        atomicAdd(&g_cnt[d * RR + r], 1);
    }
}

// tf32-round W1|root1|W2|root2 -> g_wr, x -> g_xr (one pass, every call)
__global__ void round_kernel(const float* __restrict__ x,
                             const float* __restrict__ W1, const float* __restrict__ r1,
                             const float* __restrict__ W2, const float* __restrict__ r2) {
    const int WSZ = 16 * DD * DD;   // 262144
    const int LSZ = 17 * DD * DD;   // 278528
    const int TOT = 2 * LSZ + NN * DD;
    int i = blockIdx.x * blockDim.x + threadIdx.x;
    for (; i < TOT; i += gridDim.x * blockDim.x) {
        float v;
        float* dst;
        if (i < LSZ)          { v = (i < WSZ) ? W1[i] : r1[i - WSZ];                 dst = g_wr + i; }
        else if (i < 2 * LSZ) { int j = i - LSZ; v = (j < WSZ) ? W2[j] : r2[j - WSZ]; dst = g_wr + i; }
        else                  { int j = i - 2 * LSZ; v = x[j];                        dst = g_xr + j; }
        *dst = tf32r(v);
    }
}

// single-block scan over NSEG counts; also computes g_inv
__global__ void scan_kernel() {
    __shared__ int part[1024];
    const int tid = threadIdx.x;
    const int CH = (NSEG + 1023) / 1024;  // 782
    int base = tid * CH;
    int s = 0;
    for (int j = 0; j < CH; j++) {
        int idx = base + j;
        if (idx < NSEG) s += g_cnt[idx];
    }
    part[tid] = s;
    __syncthreads();
    for (int ofs = 1; ofs < 1024; ofs <<= 1) {
        int add = (tid >= ofs) ? part[tid - ofs] : 0;
        __syncthreads();
        part[tid] += add;
        __syncthreads();
    }
    int excl = (tid > 0) ? part[tid - 1] : 0;
    int run = excl;
    for (int j = 0; j < CH; j++) {
        int idx = base + j;
        if (idx < NSEG) {
            int c = g_cnt[idx];
            g_off[idx] = run;
            g_cursor[idx] = run;
            g_inv[idx] = 1.0f / (float)(c > 1 ? c : 1);
            run += c;
        }
    }
    if (tid == 1023) g_off[NSEG] = part[1023];
}

__global__ void csr_kernel() {
    int e = blockIdx.x * blockDim.x + threadIdx.x;
    for (; e < EE; e += gridDim.x * blockDim.x) {
        unsigned long long rc = g_rec[e];
        if (rc == ~0ull) continue;
        int d = (int)(rc & 0xFFFFFu);
        int s = (int)((rc >> 20) & 0xFFFFFu);
        int r = (int)(rc >> 40);
        int pos = atomicAdd(&g_cursor[d * RR + r], 1);
        g_csr[pos] = (unsigned)s;
    }
}

// ---------------- aggregation v2: register accumulators, zero smem ----------
// block = dst node (128 threads, thread = feature column). CSR is
// (dst,rel)-sorted, so loop rel outer / edges inner with a scalar acc.
// Writes g_msg already mean-scaled and tf32-rounded.
__global__ void agg_kernel(const float* __restrict__ Xext, int use_h1) {
    const float* __restrict__ X = use_h1 ? (const float*)g_h1 : Xext;
    const int i = blockIdx.x;
    const int t = threadIdx.x;
    const int base = i * RR;
#pragma unroll
    for (int r = 0; r < RR; r++) {
        int pb = __ldg(&g_off[base + r]);
        int pe = __ldg(&g_off[base + r + 1]);
        float iv = __ldg(&g_inv[base + r]);
        float acc = 0.0f;
        for (int p = pb; p < pe; p++) {
            int s = (int)__ldg(&g_csr[p]);
            acc += __ldg(&X[(size_t)s * DD + t]);
        }
        g_msg[((size_t)r * NN + i) * DD + t] = tf32r(acc * iv);
    }
}

// ---------------- GEMM v2: cp.async double-buffered ----------------
// Y = relu([msg | xr] @ [W ; root] + bias). K = 2176 in 68 chunks of 32.
// All operands pre-rounded tf32 -> raw 16B async copies, no cvt in the loop.
#define ASTR 36
#define BSTR 132
#define SFLOATS (128 * ASTR + 32 * BSTR)     // 8832 floats per stage
#define GSMEM (2 * SFLOATS * 4)              // 70656 bytes

__global__ void __launch_bounds__(256, 2)
gemm_kernel(const float* __restrict__ bias,
            float* __restrict__ Yext,
            int io_mode,   // bit1: Y -> g_h1 ; bit2: also write tf32(Y) -> g_xr
            int lsel)      // 0: layer-1 weights, 1: layer-2 weights
{
    extern __shared__ float sm[];
    float* __restrict__ Y = (io_mode & 2) ? (float*)g_h1 : Yext;
    const float* WL = g_wr + (size_t)lsel * 17 * DD * DD;

    const int tid = threadIdx.x;
    const int lane = tid & 31;
    const int warp = tid >> 5;
    const int row0 = blockIdx.x * 128;
    const int wm = warp & 3;   // 4 warps over M (32 rows each)
    const int wn = warp >> 2;  // 2 warps over N (64 cols each)
    const uint32_t sbase = (uint32_t)__cvta_generic_to_shared(sm);

    float acc[2][8][4];
#pragma unroll
    for (int mi = 0; mi < 2; mi++)
#pragma unroll
        for (int ni = 0; ni < 8; ni++)
#pragma unroll
            for (int q = 0; q < 4; q++) acc[mi][ni][q] = 0.0f;

    auto issue = [&](int c, int stage) {
        int kglob = c * 32;
        int r = kglob >> 7;       // 0..16 (16 = root/self)
        int koff = kglob & 127;
        const float* Ab = (r < 16)
            ? (g_msg + ((size_t)r * NN + row0) * DD + koff)
            : (g_xr + (size_t)row0 * DD + koff);
        const float* Bb = WL + (size_t)r * DD * DD + (size_t)koff * DD;
        uint32_t sa = sbase + (uint32_t)(stage * SFLOATS) * 4u;
        uint32_t sb = sa + 128 * ASTR * 4;
#pragma unroll
        for (int it = 0; it < 4; it++) {
            int j = tid + 256 * it;
            int rA = j >> 3, cg = j & 7;
            int ss = (row0 + rA < NN) ? 16 : 0;   // zero-fill M tail
            cp16(sa + (uint32_t)(rA * ASTR + cg * 4) * 4u,
                 Ab + (size_t)rA * DD + cg * 4, ss);
        }
#pragma unroll
        for (int it = 0; it < 4; it++) {
            int j = tid + 256 * it;
            int rB = j >> 5, cg = j & 31;
            cp16(sb + (uint32_t)(rB * BSTR + cg * 4) * 4u,
                 Bb + (size_t)rB * DD + cg * 4, 16);
        }
        asm volatile("cp.async.commit_group;" ::: "memory");
    };

    issue(0, 0);
    for (int c = 0; c < 68; c++) {
        if (c < 67) {
            issue(c + 1, (c + 1) & 1);
            asm volatile("cp.async.wait_group 1;" ::: "memory");
        } else {
            asm volatile("cp.async.wait_group 0;" ::: "memory");
        }
        __syncthreads();

        const uint32_t* Au = (const uint32_t*)(sm + (c & 1) * SFLOATS);
        const uint32_t* Bu = Au + 128 * ASTR;
#pragma unroll
        for (int ks = 0; ks < 4; ks++) {
            int k8 = ks * 8;
            uint32_t a[2][4];
#pragma unroll
            for (int mi = 0; mi < 2; mi++) {
                int rb = wm * 32 + mi * 16 + (lane >> 2);
                int cb = k8 + (lane & 3);
                a[mi][0] = Au[rb * ASTR + cb];
                a[mi][1] = Au[(rb + 8) * ASTR + cb];
                a[mi][2] = Au[rb * ASTR + cb + 4];
                a[mi][3] = Au[(rb + 8) * ASTR + cb + 4];
            }
            uint32_t b[8][2];
#pragma unroll
            for (int ni = 0; ni < 8; ni++) {
                int col = wn * 64 + ni * 8 + (lane >> 2);
                int kb = k8 + (lane & 3);
                b[ni][0] = Bu[kb * BSTR + col];
                b[ni][1] = Bu[(kb + 4) * BSTR + col];
            }
#pragma unroll
            for (int mi = 0; mi < 2; mi++)
#pragma unroll
                for (int ni = 0; ni < 8; ni++)
                    mma8(acc[mi][ni], a[mi], b[ni]);
        }
        __syncthreads();
    }

    // epilogue: + bias, relu, store (+ rounded copy for next layer's root term)
    const bool wr_xr = (io_mode & 4) != 0;
#pragma unroll
    for (int mi = 0; mi < 2; mi++) {
        int r0 = row0 + wm * 32 + mi * 16 + (lane >> 2);
#pragma unroll
        for (int ni = 0; ni < 8; ni++) {
            int cc = wn * 64 + ni * 8 + (lane & 3) * 2;
            float bi0 = __ldg(&bias[cc]);
            float bi1 = __ldg(&bias[cc + 1]);
            if (r0 < NN) {
                float y0 = fmaxf(acc[mi][ni][0] + bi0, 0.0f);
                float y1 = fmaxf(acc[mi][ni][1] + bi1, 0.0f);
                *(float2*)(Y + (size_t)r0 * DD + cc) = make_float2(y0, y1);
                if (wr_xr)
                    *(float2*)(g_xr + (size_t)r0 * DD + cc) =
                        make_float2(tf32r(y0), tf32r(y1));
            }
            if (r0 + 8 < NN) {
                float y2 = fmaxf(acc[mi][ni][2] + bi0, 0.0f);
                float y3 = fmaxf(acc[mi][ni][3] + bi1, 0.0f);
                *(float2*)(Y + (size_t)(r0 + 8) * DD + cc) = make_float2(y2, y3);
                if (wr_xr)
                    *(float2*)(g_xr + (size_t)(r0 + 8) * DD + cc) =
                        make_float2(tf32r(y2), tf32r(y3));
            }
        }
    }
}

// ---------------- launch ----------------
extern "C" void kernel_launch(void* const* d_in, const int* in_sizes, int n_in,
                              void* d_out, int out_size) {
    const float* x     = (const float*)d_in[0];
    const void*  ei    = d_in[1];   // int32 or int64, detected on device
    const void*  et    = d_in[2];
    const float* W1    = (const float*)d_in[3];
    const float* root1 = (const float*)d_in[4];
    const float* b1    = (const float*)d_in[5];
    const float* W2    = (const float*)d_in[6];
    const float* root2 = (const float*)d_in[7];
    const float* b2    = (const float*)d_in[8];
    float* out         = (float*)d_out;

    cudaFuncSetAttribute(gemm_kernel,
                         cudaFuncAttributeMaxDynamicSharedMemorySize, GSMEM);

    // structure (shared by both layers)
    detect_kernel<<<1, 256>>>((const unsigned int*)et);
    zero_cnt_kernel<<<1024, 256>>>();
    count_kernel<<<2048, 256>>>(ei, et);
    round_kernel<<<2048, 256>>>(x, W1, root1, W2, root2);
    scan_kernel<<<1, 1024>>>();
    csr_kernel<<<2048, 256>>>();

    const int gemm_blocks = (NN + 127) / 128;  // 391

    // layer 1: agg from x; gemm -> g_h1 (raw) + g_xr (rounded)
    agg_kernel<<<NN, 128>>>(x, 0);
    gemm_kernel<<<gemm_blocks, 256, GSMEM>>>(b1, out, /*io_mode=*/2 | 4, /*lsel=*/0);

    // layer 2: agg from g_h1; gemm -> d_out
    agg_kernel<<<NN, 128>>>(nullptr, 1);
    gemm_kernel<<<gemm_blocks, 256, GSMEM>>>(b2, out, /*io_mode=*/0, /*lsel=*/1);
}